// round 2
// baseline (speedup 1.0000x reference)
#include <cuda_runtime.h>

// out[i] = floorf(image[i] * 0.5f) — HBM-bound streaming.
// 4x float4 per thread (front-batched loads -> MLP=4 per thread),
// evict-first cache hints since working set (201MB) > L2 (126MB).

#define V4_PER_THREAD 4

__global__ void __launch_bounds__(256) stego_halve_kernel(
    const float4* __restrict__ in, float4* __restrict__ out, int n4)
{
    int base = (blockIdx.x * blockDim.x + threadIdx.x) * V4_PER_THREAD;

    if (base + V4_PER_THREAD <= n4) {
        float4 v[V4_PER_THREAD];
        #pragma unroll
        for (int j = 0; j < V4_PER_THREAD; j++)
            v[j] = __ldcs(&in[base + j]);          // batched independent LDG.128
        #pragma unroll
        for (int j = 0; j < V4_PER_THREAD; j++) {
            float4 r;
            r.x = floorf(v[j].x * 0.5f);
            r.y = floorf(v[j].y * 0.5f);
            r.z = floorf(v[j].z * 0.5f);
            r.w = floorf(v[j].w * 0.5f);
            __stcs(&out[base + j], r);             // evict-first stores
        }
    } else {
        for (int j = 0; j < V4_PER_THREAD; j++) {
            int i = base + j;
            if (i < n4) {
                float4 v = __ldcs(&in[i]);
                float4 r;
                r.x = floorf(v.x * 0.5f);
                r.y = floorf(v.y * 0.5f);
                r.z = floorf(v.z * 0.5f);
                r.w = floorf(v.w * 0.5f);
                __stcs(&out[i], r);
            }
        }
    }
}

extern "C" void kernel_launch(void* const* d_in, const int* in_sizes, int n_in,
                              void* d_out, int out_size)
{
    const float* img = (const float*)d_in[0];
    float* out = (float*)d_out;
    int n = in_sizes[0];                 // 25,165,824
    int n4 = n / 4;                      // divisible by 4
    int threads = 256;
    int elems_per_block = threads * V4_PER_THREAD;
    int blocks = (n4 + elems_per_block - 1) / elems_per_block;
    stego_halve_kernel<<<blocks, threads>>>((const float4*)img, (float4*)out, n4);
}

// round 4
// speedup vs baseline: 1.1395x; 1.1395x over previous
#include <cuda_runtime.h>

// out[i] = floorf(image[i] * 0.5f) — HBM-bound streaming.
// MLP=4 per thread with WARP-COALESCED layout: each of the 4 loads per
// thread is a fully dense warp access (offsets t + k*blockDim), unlike the
// per-thread-contiguous R2 variant which fragmented coalescing.

#define VPT 4  // float4s per thread

__global__ void __launch_bounds__(256) stego_halve_kernel(
    const float4* __restrict__ in, float4* __restrict__ out, int n4)
{
    const int tpb = 256;
    int blockBase = blockIdx.x * (tpb * VPT);
    int t = threadIdx.x;

    if (blockBase + tpb * VPT <= n4) {
        float4 v[VPT];
        #pragma unroll
        for (int k = 0; k < VPT; k++)
            v[k] = __ldcs(&in[blockBase + t + k * tpb]);   // 4 independent coalesced LDG.128
        #pragma unroll
        for (int k = 0; k < VPT; k++) {
            float4 r;
            r.x = floorf(v[k].x * 0.5f);
            r.y = floorf(v[k].y * 0.5f);
            r.z = floorf(v[k].z * 0.5f);
            r.w = floorf(v[k].w * 0.5f);
            __stcs(&out[blockBase + t + k * tpb], r);
        }
    } else {
        #pragma unroll
        for (int k = 0; k < VPT; k++) {
            int i = blockBase + t + k * tpb;
            if (i < n4) {
                float4 v = __ldcs(&in[i]);
                float4 r;
                r.x = floorf(v.x * 0.5f);
                r.y = floorf(v.y * 0.5f);
                r.z = floorf(v.z * 0.5f);
                r.w = floorf(v.w * 0.5f);
                __stcs(&out[i], r);
            }
        }
    }
}

extern "C" void kernel_launch(void* const* d_in, const int* in_sizes, int n_in,
                              void* d_out, int out_size)
{
    const float* img = (const float*)d_in[0];
    float* out = (float*)d_out;
    int n = in_sizes[0];                 // 25,165,824
    int n4 = n / 4;
    int threads = 256;
    int elems_per_block = threads * VPT;
    int blocks = (n4 + elems_per_block - 1) / elems_per_block;
    stego_halve_kernel<<<blocks, threads>>>((const float4*)img, (float4*)out, n4);
}

// round 5
// speedup vs baseline: 1.1604x; 1.0183x over previous
#include <cuda_runtime.h>

// out[i] = floorf(image[i] * 0.5f) — HBM-bound streaming.
// MLP=8 per thread, warp-coalesced (offset t + k*blockDim): 8 independent
// dense LDG.128s front-batched per thread to maximize memory queue depth.
// Evict-first hints: 201MB stream > 126MB L2, no reuse.

#define VPT 8  // float4s per thread

__global__ void __launch_bounds__(256) stego_halve_kernel(
    const float4* __restrict__ in, float4* __restrict__ out, int n4)
{
    const int tpb = 256;
    int blockBase = blockIdx.x * (tpb * VPT);
    int t = threadIdx.x;

    if (blockBase + tpb * VPT <= n4) {
        float4 v[VPT];
        #pragma unroll
        for (int k = 0; k < VPT; k++)
            v[k] = __ldcs(&in[blockBase + t + k * tpb]);   // 8 independent coalesced LDG.128
        #pragma unroll
        for (int k = 0; k < VPT; k++) {
            float4 r;
            r.x = floorf(v[k].x * 0.5f);
            r.y = floorf(v[k].y * 0.5f);
            r.z = floorf(v[k].z * 0.5f);
            r.w = floorf(v[k].w * 0.5f);
            __stcs(&out[blockBase + t + k * tpb], r);
        }
    } else {
        #pragma unroll
        for (int k = 0; k < VPT; k++) {
            int i = blockBase + t + k * tpb;
            if (i < n4) {
                float4 v = __ldcs(&in[i]);
                float4 r;
                r.x = floorf(v.x * 0.5f);
                r.y = floorf(v.y * 0.5f);
                r.z = floorf(v.z * 0.5f);
                r.w = floorf(v.w * 0.5f);
                __stcs(&out[i], r);
            }
        }
    }
}

extern "C" void kernel_launch(void* const* d_in, const int* in_sizes, int n_in,
                              void* d_out, int out_size)
{
    const float* img = (const float*)d_in[0];
    float* out = (float*)d_out;
    int n = in_sizes[0];                 // 25,165,824
    int n4 = n / 4;
    int threads = 256;
    int elems_per_block = threads * VPT;
    int blocks = (n4 + elems_per_block - 1) / elems_per_block;
    stego_halve_kernel<<<blocks, threads>>>((const float4*)img, (float4*)out, n4);
}